// round 1
// baseline (speedup 1.0000x reference)
#include <cuda_runtime.h>
#include <cstdint>

#define N_NODES 65536
#define N_EDGES 1048576
#define EMB 64
#define IN_DIM 128
#define OUT_DIM 32
#define N_HIDDEN 4

// ---------------- scratch (static device globals; no allocation) ----------------
__device__ float g_h[N_NODES * EMB];        // layer activations
__device__ float g_hw[N_NODES * EMB];       // post-GEMM, pre-aggregation
__device__ float g_dinv[N_NODES];           // 1/sqrt(deg)
__device__ int   g_count[N_NODES];          // in-degree histogram
__device__ int   g_rowptr[N_NODES + 1];     // CSR row pointers (by dst)
__device__ int   g_fill[N_NODES];           // fill cursors
__device__ int   g_csr_src[N_EDGES];        // CSR: source node per slot
__device__ float g_csr_w[N_EDGES];          // CSR: edge weight, later normalized
__device__ int   g_is64;                    // edge_index dtype flag

// ---------------- dtype detection ----------------
// int64 little-endian with values < 2^31 => every odd int32 word is 0.
// int32 data: odd words are random src indices, ~all nonzero.
__global__ void detect_kernel(const unsigned int* __restrict__ w) {
    __shared__ int s_any;
    if (threadIdx.x == 0) s_any = 0;
    __syncthreads();
    unsigned int v = w[2 * threadIdx.x + 1];  // idx <= 255, in-bounds either way
    if (v != 0) s_any = 1;
    __syncthreads();
    if (threadIdx.x == 0) g_is64 = (s_any == 0) ? 1 : 0;
}

__device__ __forceinline__ int load_idx(const void* p, int i) {
    if (g_is64) return (int)((const long long*)p)[i];
    return ((const int*)p)[i];
}

// ---------------- CSR construction ----------------
__global__ void init_kernel() {
    int i = blockIdx.x * blockDim.x + threadIdx.x;
    if (i < N_NODES) { g_count[i] = 0; g_fill[i] = 0; }
}

__global__ void count_kernel(const void* __restrict__ eidx) {
    int e = blockIdx.x * blockDim.x + threadIdx.x;
    if (e >= N_EDGES) return;
    int dst = load_idx(eidx, N_EDGES + e);
    atomicAdd(&g_count[dst], 1);
}

// one block, 1024 threads; each thread handles 64 consecutive counts
__global__ void scan_kernel() {
    __shared__ int s[1024];
    int t = threadIdx.x;
    int base = t * 64;
    int sum = 0;
#pragma unroll
    for (int j = 0; j < 64; j++) sum += g_count[base + j];
    s[t] = sum;
    __syncthreads();
    for (int off = 1; off < 1024; off <<= 1) {
        int v = (t >= off) ? s[t - off] : 0;
        __syncthreads();
        s[t] += v;
        __syncthreads();
    }
    int run = (t == 0) ? 0 : s[t - 1];
#pragma unroll
    for (int j = 0; j < 64; j++) {
        g_rowptr[base + j] = run;
        run += g_count[base + j];
    }
    if (t == 1023) g_rowptr[N_NODES] = run;
}

__global__ void fill_kernel(const void* __restrict__ eidx,
                            const float* __restrict__ ew) {
    int e = blockIdx.x * blockDim.x + threadIdx.x;
    if (e >= N_EDGES) return;
    int src = load_idx(eidx, e);
    int dst = load_idx(eidx, N_EDGES + e);
    int pos = g_rowptr[dst] + atomicAdd(&g_fill[dst], 1);
    g_csr_src[pos] = src;
    g_csr_w[pos] = ew[e];
}

// warp per node: deg = 1 (self loop) + sum of incoming edge weights; dinv = rsqrt(deg)
__global__ void deg_dinv_kernel() {
    int wg = (blockIdx.x * blockDim.x + threadIdx.x) >> 5;
    int lane = threadIdx.x & 31;
    if (wg >= N_NODES) return;
    int s0 = g_rowptr[wg], s1 = g_rowptr[wg + 1];
    float sum = 0.f;
    for (int e = s0 + lane; e < s1; e += 32) sum += g_csr_w[e];
#pragma unroll
    for (int off = 16; off > 0; off >>= 1)
        sum += __shfl_down_sync(0xffffffffu, sum, off);
    if (lane == 0) {
        float d = 1.0f + sum;  // always > 0
        float r = rsqrtf(d);
        r = r * (1.5f - 0.5f * d * r * r);  // Newton refine
        g_dinv[wg] = r;
    }
}

// warp per node: csr_w[e] = dinv[dst] * ew * dinv[src]
__global__ void scale_kernel() {
    int wg = (blockIdx.x * blockDim.x + threadIdx.x) >> 5;
    int lane = threadIdx.x & 31;
    if (wg >= N_NODES) return;
    float di = g_dinv[wg];
    int s0 = g_rowptr[wg], s1 = g_rowptr[wg + 1];
    for (int e = s0 + lane; e < s1; e += 32)
        g_csr_w[e] = g_csr_w[e] * di * g_dinv[g_csr_src[e]];
}

// ---------------- GEMM: C[N,64] = A[N,K] @ W[K,64] ----------------
template <int K>
__global__ __launch_bounds__(256) void gemm_n64_kernel(
    const float* __restrict__ A, const float* __restrict__ W,
    float* __restrict__ C) {
    __shared__ float sw[K * 64];
    int tid = threadIdx.x, lane = tid & 31, warp = tid >> 5;
    for (int i = tid; i < K * 64; i += 256) sw[i] = W[i];
    __syncthreads();
    int row = blockIdx.x * 64 + warp * 8;
    for (int rr = 0; rr < 8; rr++, row++) {
        const float* a = A + (size_t)row * K;
        float ar[K / 32];
#pragma unroll
        for (int j = 0; j < K / 32; j++) ar[j] = a[lane + 32 * j];
        float acc0 = 0.f, acc1 = 0.f;
#pragma unroll
        for (int k = 0; k < K; k++) {
            float av = __shfl_sync(0xffffffffu, ar[k >> 5], k & 31);
            acc0 = fmaf(av, sw[k * 64 + lane], acc0);
            acc1 = fmaf(av, sw[k * 64 + lane + 32], acc1);
        }
        float* c = C + (size_t)row * 64;
        c[lane] = acc0;
        c[lane + 32] = acc1;
    }
}

// ---------------- aggregation + bias + ELU (warp per dst) ----------------
__global__ __launch_bounds__(256) void agg_elu_kernel(
    const float* __restrict__ hw, const float* __restrict__ bias) {
    int i = (blockIdx.x * blockDim.x + threadIdx.x) >> 5;
    int lane = threadIdx.x & 31;
    if (i >= N_NODES) return;
    float di = g_dinv[i];
    float wself = di * di;
    const float* hr = hw + (size_t)i * 64;
    float acc0 = wself * hr[lane];
    float acc1 = wself * hr[lane + 32];
    int e = g_rowptr[i], s1 = g_rowptr[i + 1];
    for (; e + 1 < s1; e += 2) {
        int sA = g_csr_src[e], sB = g_csr_src[e + 1];
        float wA = g_csr_w[e], wB = g_csr_w[e + 1];
        const float* rA = hw + (size_t)sA * 64;
        const float* rB = hw + (size_t)sB * 64;
        float a0 = rA[lane], a1 = rA[lane + 32];
        float b0 = rB[lane], b1 = rB[lane + 32];
        acc0 = fmaf(wA, a0, acc0);
        acc1 = fmaf(wA, a1, acc1);
        acc0 = fmaf(wB, b0, acc0);
        acc1 = fmaf(wB, b1, acc1);
    }
    if (e < s1) {
        int s = g_csr_src[e];
        float w = g_csr_w[e];
        const float* r = hw + (size_t)s * 64;
        acc0 = fmaf(w, r[lane], acc0);
        acc1 = fmaf(w, r[lane + 32], acc1);
    }
    acc0 += bias[lane];
    acc1 += bias[lane + 32];
    acc0 = acc0 > 0.f ? acc0 : expm1f(acc0);
    acc1 = acc1 > 0.f ? acc1 : expm1f(acc1);
    g_h[(size_t)i * 64 + lane] = acc0;
    g_h[(size_t)i * 64 + lane + 32] = acc1;
}

// ---------------- final linear 64->32 + ReLU (warp per row) ----------------
__global__ __launch_bounds__(256) void final_lin_kernel(
    const float* __restrict__ W, const float* __restrict__ b,
    float* __restrict__ out) {
    __shared__ float sw[64 * 32];
    int tid = threadIdx.x, lane = tid & 31;
    for (int i = tid; i < 64 * 32; i += 256) sw[i] = W[i];
    __syncthreads();
    int row = (blockIdx.x * blockDim.x + tid) >> 5;
    if (row >= N_NODES) return;
    const float* h = g_h + (size_t)row * 64;
    float a0 = h[lane], a1 = h[lane + 32];
    float acc = b[lane];
#pragma unroll
    for (int k = 0; k < 64; k++) {
        float av = __shfl_sync(0xffffffffu, (k < 32) ? a0 : a1, k & 31);
        acc = fmaf(av, sw[k * 32 + lane], acc);
    }
    out[(size_t)row * 32 + lane] = acc > 0.f ? acc : 0.f;
}

// ---------------- launch ----------------
extern "C" void kernel_launch(void* const* d_in, const int* in_sizes, int n_in,
                              void* d_out, int out_size) {
    const float* x      = (const float*)d_in[0];
    const void*  eidx   = d_in[1];
    const float* ew     = (const float*)d_in[2];
    const float* W1     = (const float*)d_in[3];
    const float* b1     = (const float*)d_in[4];
    const float* W_hid  = (const float*)d_in[5];
    const float* b_hid  = (const float*)d_in[6];
    const float* W_lin  = (const float*)d_in[7];
    const float* b_lin  = (const float*)d_in[8];
    float* out = (float*)d_out;

    float *h_ptr, *hw_ptr;
    cudaGetSymbolAddress((void**)&h_ptr, g_h);
    cudaGetSymbolAddress((void**)&hw_ptr, g_hw);

    // ---- graph preprocessing (per call; deterministic) ----
    detect_kernel<<<1, 128>>>((const unsigned int*)eidx);
    init_kernel<<<N_NODES / 256, 256>>>();
    count_kernel<<<N_EDGES / 256, 256>>>(eidx);
    scan_kernel<<<1, 1024>>>();
    fill_kernel<<<N_EDGES / 256, 256>>>(eidx, ew);
    deg_dinv_kernel<<<N_NODES / 8, 256>>>();
    scale_kernel<<<N_NODES / 8, 256>>>();

    // ---- layer 1: 128 -> 64 ----
    gemm_n64_kernel<IN_DIM><<<N_NODES / 64, 256>>>(x, W1, hw_ptr);
    agg_elu_kernel<<<N_NODES / 8, 256>>>(hw_ptr, b1);

    // ---- hidden layers: 64 -> 64 ----
    for (int l = 0; l < N_HIDDEN; l++) {
        gemm_n64_kernel<EMB><<<N_NODES / 64, 256>>>(
            h_ptr, W_hid + (size_t)l * EMB * EMB, hw_ptr);
        agg_elu_kernel<<<N_NODES / 8, 256>>>(hw_ptr, b_hid + (size_t)l * EMB);
    }

    // ---- final linear 64 -> 32 + ReLU ----
    final_lin_kernel<<<N_NODES / 8, 256>>>(W_lin, b_lin, out);
}

// round 2
// speedup vs baseline: 1.2272x; 1.2272x over previous
#include <cuda_runtime.h>
#include <cstdint>

#define N_NODES 65536
#define N_EDGES 1048576
#define EMB 64
#define IN_DIM 128
#define OUT_DIM 32
#define N_HIDDEN 4
#define N_CHUNKS 1024   // 65536 / 64

// ---------------- scratch (static device globals; no allocation) ----------------
__device__ float g_h[N_NODES * EMB];        // layer activations
__device__ float g_hw[N_NODES * EMB];       // post-GEMM, pre-aggregation
__device__ float g_dinv[N_NODES];           // 1/sqrt(deg)
__device__ int   g_count[N_NODES];          // in-degree histogram
__device__ int   g_rowptr[N_NODES + 1];     // CSR row pointers (by dst)
__device__ int   g_fill[N_NODES];           // fill cursors
__device__ int   g_csr_src[N_EDGES];        // CSR: source node per slot
__device__ float g_csr_w[N_EDGES];          // CSR: edge weight, later normalized
__device__ int   g_choff[N_CHUNKS];         // exclusive chunk offsets
__device__ int   g_part[N_CHUNKS];          // chunk partial sums
__device__ int   g_is64;                    // edge_index dtype flag

// ---------------- dtype detection ----------------
// int64 little-endian with values < 2^31 => every odd int32 word is 0.
__global__ void detect_kernel(const unsigned int* __restrict__ w) {
    __shared__ int s_any;
    if (threadIdx.x == 0) s_any = 0;
    __syncthreads();
    unsigned int v = w[2 * threadIdx.x + 1];
    if (v != 0) s_any = 1;
    __syncthreads();
    if (threadIdx.x == 0) g_is64 = (s_any == 0) ? 1 : 0;
}

__device__ __forceinline__ int load_idx(const void* p, int i) {
    if (g_is64) return (int)((const long long*)p)[i];
    return ((const int*)p)[i];
}

// ---------------- CSR construction ----------------
__global__ void count_kernel(const void* __restrict__ eidx) {
    int e = blockIdx.x * blockDim.x + threadIdx.x;
    if (e >= N_EDGES) return;
    int dst = load_idx(eidx, N_EDGES + e);
    atomicAdd(&g_count[dst], 1);
}

// phase 1: warp per 64-element chunk -> partial sum
__global__ void chunk_reduce_kernel() {
    int warp = (blockIdx.x * blockDim.x + threadIdx.x) >> 5;
    int lane = threadIdx.x & 31;
    if (warp >= N_CHUNKS) return;
    int base = warp * 64;
    int v = g_count[base + lane] + g_count[base + 32 + lane];
#pragma unroll
    for (int off = 16; off > 0; off >>= 1)
        v += __shfl_down_sync(0xffffffffu, v, off);
    if (lane == 0) g_part[warp] = v;
}

// phase 2: single block scans 1024 partials -> exclusive chunk offsets
__global__ void scan_part_kernel() {
    __shared__ int s[N_CHUNKS];
    int t = threadIdx.x;
    int orig = g_part[t];
    s[t] = orig;
    __syncthreads();
    for (int off = 1; off < N_CHUNKS; off <<= 1) {
        int v = (t >= off) ? s[t - off] : 0;
        __syncthreads();
        s[t] += v;
        __syncthreads();
    }
    g_choff[t] = s[t] - orig;  // exclusive
}

// phase 3: warp per chunk -> rowptr via in-warp exclusive scan
__global__ void rowptr_kernel() {
    int warp = (blockIdx.x * blockDim.x + threadIdx.x) >> 5;
    int lane = threadIdx.x & 31;
    if (warp >= N_CHUNKS) return;
    int base = warp * 64;
    int c0 = g_count[base + lane];
    int c1 = g_count[base + 32 + lane];
    int i0 = c0, i1 = c1;
#pragma unroll
    for (int off = 1; off < 32; off <<= 1) {
        int v0 = __shfl_up_sync(0xffffffffu, i0, off);
        int v1 = __shfl_up_sync(0xffffffffu, i1, off);
        if (lane >= off) { i0 += v0; i1 += v1; }
    }
    int tot0 = __shfl_sync(0xffffffffu, i0, 31);
    int off = g_choff[warp];
    g_rowptr[base + lane] = off + i0 - c0;
    g_rowptr[base + 32 + lane] = off + tot0 + i1 - c1;
    if (warp == N_CHUNKS - 1 && lane == 31) g_rowptr[N_NODES] = N_EDGES;
}

__global__ void fill_kernel(const void* __restrict__ eidx,
                            const float* __restrict__ ew) {
    int e = blockIdx.x * blockDim.x + threadIdx.x;
    if (e >= N_EDGES) return;
    int src = load_idx(eidx, e);
    int dst = load_idx(eidx, N_EDGES + e);
    int pos = g_rowptr[dst] + atomicAdd(&g_fill[dst], 1);
    g_csr_src[pos] = src;
    g_csr_w[pos] = ew[e];
}

// warp per node: deg = 1 (self loop) + sum of incoming edge weights; dinv = rsqrt(deg)
__global__ void deg_dinv_kernel() {
    int wg = (blockIdx.x * blockDim.x + threadIdx.x) >> 5;
    int lane = threadIdx.x & 31;
    if (wg >= N_NODES) return;
    int s0 = g_rowptr[wg], s1 = g_rowptr[wg + 1];
    float sum = 0.f;
    for (int e = s0 + lane; e < s1; e += 32) sum += g_csr_w[e];
#pragma unroll
    for (int off = 16; off > 0; off >>= 1)
        sum += __shfl_down_sync(0xffffffffu, sum, off);
    if (lane == 0) {
        float d = 1.0f + sum;  // always > 0
        float r = rsqrtf(d);
        r = r * (1.5f - 0.5f * d * r * r);  // Newton refine
        g_dinv[wg] = r;
    }
}

// warp per node: csr_w[e] = dinv[dst] * ew * dinv[src]
__global__ void scale_kernel() {
    int wg = (blockIdx.x * blockDim.x + threadIdx.x) >> 5;
    int lane = threadIdx.x & 31;
    if (wg >= N_NODES) return;
    float di = g_dinv[wg];
    int s0 = g_rowptr[wg], s1 = g_rowptr[wg + 1];
    for (int e = s0 + lane; e < s1; e += 32)
        g_csr_w[e] = g_csr_w[e] * di * g_dinv[g_csr_src[e]];
}

// ---------------- GEMM: C[N,64] = A[N,K] @ W[K,64] ----------------
template <int K>
__global__ __launch_bounds__(256) void gemm_n64_kernel(
    const float* __restrict__ A, const float* __restrict__ W,
    float* __restrict__ C) {
    __shared__ float sw[K * 64];
    int tid = threadIdx.x, lane = tid & 31, warp = tid >> 5;
    for (int i = tid; i < K * 64; i += 256) sw[i] = W[i];
    __syncthreads();
    int row = blockIdx.x * 64 + warp * 8;
    for (int rr = 0; rr < 8; rr++, row++) {
        const float* a = A + (size_t)row * K;
        float ar[K / 32];
#pragma unroll
        for (int j = 0; j < K / 32; j++) ar[j] = a[lane + 32 * j];
        float acc0 = 0.f, acc1 = 0.f;
#pragma unroll
        for (int k = 0; k < K; k++) {
            float av = __shfl_sync(0xffffffffu, ar[k >> 5], k & 31);
            acc0 = fmaf(av, sw[k * 64 + lane], acc0);
            acc1 = fmaf(av, sw[k * 64 + lane + 32], acc1);
        }
        float* c = C + (size_t)row * 64;
        c[lane] = acc0;
        c[lane + 32] = acc1;
    }
}

// ---------------- aggregation + bias + ELU (warp per dst, float2 gathers) ----------------
__global__ __launch_bounds__(256) void agg_elu_kernel(
    const float* __restrict__ hw, const float* __restrict__ bias) {
    int i = (blockIdx.x * blockDim.x + threadIdx.x) >> 5;
    int lane = threadIdx.x & 31;
    if (i >= N_NODES) return;
    const float2* hw2 = (const float2*)hw;  // row stride = 32 float2
    float di = g_dinv[i];
    float wself = di * di;
    float2 hr = hw2[(size_t)i * 32 + lane];
    float acc0 = wself * hr.x;
    float acc1 = wself * hr.y;
    int e = g_rowptr[i], s1 = g_rowptr[i + 1];
    for (; e + 1 < s1; e += 2) {
        int sA = g_csr_src[e], sB = g_csr_src[e + 1];
        float wA = g_csr_w[e], wB = g_csr_w[e + 1];
        float2 a = hw2[(size_t)sA * 32 + lane];
        float2 b = hw2[(size_t)sB * 32 + lane];
        acc0 = fmaf(wA, a.x, acc0);
        acc1 = fmaf(wA, a.y, acc1);
        acc0 = fmaf(wB, b.x, acc0);
        acc1 = fmaf(wB, b.y, acc1);
    }
    if (e < s1) {
        int s = g_csr_src[e];
        float w = g_csr_w[e];
        float2 a = hw2[(size_t)s * 32 + lane];
        acc0 = fmaf(w, a.x, acc0);
        acc1 = fmaf(w, a.y, acc1);
    }
    const float2* b2 = (const float2*)bias;
    float2 bb = b2[lane];
    acc0 += bb.x;
    acc1 += bb.y;
    acc0 = acc0 > 0.f ? acc0 : expm1f(acc0);
    acc1 = acc1 > 0.f ? acc1 : expm1f(acc1);
    ((float2*)g_h)[(size_t)i * 32 + lane] = make_float2(acc0, acc1);
}

// ---------------- final linear 64->32 + ReLU (warp per row) ----------------
__global__ __launch_bounds__(256) void final_lin_kernel(
    const float* __restrict__ W, const float* __restrict__ b,
    float* __restrict__ out) {
    __shared__ float sw[64 * 32];
    int tid = threadIdx.x, lane = tid & 31;
    for (int i = tid; i < 64 * 32; i += 256) sw[i] = W[i];
    __syncthreads();
    int row = (blockIdx.x * blockDim.x + tid) >> 5;
    if (row >= N_NODES) return;
    const float* h = g_h + (size_t)row * 64;
    float a0 = h[lane], a1 = h[lane + 32];
    float acc = b[lane];
#pragma unroll
    for (int k = 0; k < 64; k++) {
        float av = __shfl_sync(0xffffffffu, (k < 32) ? a0 : a1, k & 31);
        acc = fmaf(av, sw[k * 32 + lane], acc);
    }
    out[(size_t)row * 32 + lane] = acc > 0.f ? acc : 0.f;
}

// ---------------- launch ----------------
extern "C" void kernel_launch(void* const* d_in, const int* in_sizes, int n_in,
                              void* d_out, int out_size) {
    const float* x      = (const float*)d_in[0];
    const void*  eidx   = d_in[1];
    const float* ew     = (const float*)d_in[2];
    const float* W1     = (const float*)d_in[3];
    const float* b1     = (const float*)d_in[4];
    const float* W_hid  = (const float*)d_in[5];
    const float* b_hid  = (const float*)d_in[6];
    const float* W_lin  = (const float*)d_in[7];
    const float* b_lin  = (const float*)d_in[8];
    float* out = (float*)d_out;

    float *h_ptr, *hw_ptr;
    void *count_ptr, *fill_ptr;
    cudaGetSymbolAddress((void**)&h_ptr, g_h);
    cudaGetSymbolAddress((void**)&hw_ptr, g_hw);
    cudaGetSymbolAddress(&count_ptr, g_count);
    cudaGetSymbolAddress(&fill_ptr, g_fill);

    // ---- graph preprocessing (per call; deterministic) ----
    detect_kernel<<<1, 128>>>((const unsigned int*)eidx);
    cudaMemsetAsync(count_ptr, 0, N_NODES * sizeof(int));
    cudaMemsetAsync(fill_ptr, 0, N_NODES * sizeof(int));
    count_kernel<<<N_EDGES / 256, 256>>>(eidx);
    chunk_reduce_kernel<<<N_CHUNKS / 8, 256>>>();
    scan_part_kernel<<<1, N_CHUNKS>>>();
    rowptr_kernel<<<N_CHUNKS / 8, 256>>>();
    fill_kernel<<<N_EDGES / 256, 256>>>(eidx, ew);
    deg_dinv_kernel<<<N_NODES / 8, 256>>>();
    scale_kernel<<<N_NODES / 8, 256>>>();

    // ---- layer 1: 128 -> 64 ----
    gemm_n64_kernel<IN_DIM><<<N_NODES / 64, 256>>>(x, W1, hw_ptr);
    agg_elu_kernel<<<N_NODES / 8, 256>>>(hw_ptr, b1);

    // ---- hidden layers: 64 -> 64 ----
    for (int l = 0; l < N_HIDDEN; l++) {
        gemm_n64_kernel<EMB><<<N_NODES / 64, 256>>>(
            h_ptr, W_hid + (size_t)l * EMB * EMB, hw_ptr);
        agg_elu_kernel<<<N_NODES / 8, 256>>>(hw_ptr, b_hid + (size_t)l * EMB);
    }

    // ---- final linear 64 -> 32 + ReLU ----
    final_lin_kernel<<<N_NODES / 8, 256>>>(W_lin, b_lin, out);
}

// round 5
// speedup vs baseline: 1.2323x; 1.0041x over previous
#include <cuda_runtime.h>
#include <cstdint>

#define N_NODES 65536
#define N_EDGES 1048576
#define EMB 64
#define IN_DIM 128
#define OUT_DIM 32
#define N_HIDDEN 4
#define N_CHUNKS 1024   // 65536 / 64

// ---------------- scratch (static device globals; no allocation) ----------------
__device__ float g_h[N_NODES * EMB];        // layer activations
__device__ float g_hw[N_NODES * EMB];       // post-GEMM, pre-aggregation
__device__ float g_dinv[N_NODES];           // 1/sqrt(deg)
__device__ float g_deg[N_NODES];            // weighted in-degree (atomic float)
__device__ int   g_count[N_NODES];          // in-degree histogram
__device__ int   g_rowptr[N_NODES + 1];     // CSR row pointers (by dst)
__device__ int   g_work[N_NODES];           // fill cursors (copy of rowptr)
__device__ int2  g_csr[N_EDGES];            // CSR: {src, float_bits(norm_w)}
__device__ int   g_choff[N_CHUNKS];         // exclusive chunk offsets
__device__ int   g_part[N_CHUNKS];          // chunk partial sums
__device__ int   g_is64;                    // edge_index dtype flag

// ---------------- dtype detection ----------------
// int64 little-endian with values < 2^31 => every odd int32 word is 0.
__global__ void detect_kernel(const unsigned int* __restrict__ w) {
    __shared__ int s_any;
    if (threadIdx.x == 0) s_any = 0;
    __syncthreads();
    unsigned int v = w[2 * threadIdx.x + 1];  // tid<128 -> idx<=255, in-bounds either way
    if (v != 0) s_any = 1;
    __syncthreads();
    if (threadIdx.x == 0) g_is64 = (s_any == 0) ? 1 : 0;
}

__device__ __forceinline__ int load_idx(const void* p, int i) {
    if (g_is64) return (int)((const long long*)p)[i];
    return ((const int*)p)[i];
}

// ---------------- pass 1: count + weighted degree ----------------
__global__ void count_deg_kernel(const void* __restrict__ eidx,
                                 const float* __restrict__ ew) {
    int e = blockIdx.x * blockDim.x + threadIdx.x;
    if (e >= N_EDGES) return;
    int dst = load_idx(eidx, N_EDGES + e);
    atomicAdd(&g_count[dst], 1);
    atomicAdd(&g_deg[dst], ew[e]);
}

// ---------------- scan phase 1: warp per 64-element chunk -> partial sum ----------------
__global__ void chunk_reduce_kernel() {
    int warp = (blockIdx.x * blockDim.x + threadIdx.x) >> 5;
    int lane = threadIdx.x & 31;
    if (warp >= N_CHUNKS) return;
    int base = warp * 64;
    int v = g_count[base + lane] + g_count[base + 32 + lane];
#pragma unroll
    for (int off = 16; off > 0; off >>= 1)
        v += __shfl_down_sync(0xffffffffu, v, off);
    if (lane == 0) g_part[warp] = v;
}

// ---------------- scan phase 2: single block scans 1024 partials ----------------
__global__ void scan_part_kernel() {
    __shared__ int s[N_CHUNKS];
    int t = threadIdx.x;
    int orig = g_part[t];
    s[t] = orig;
    __syncthreads();
    for (int off = 1; off < N_CHUNKS; off <<= 1) {
        int v = (t >= off) ? s[t - off] : 0;
        __syncthreads();
        s[t] += v;
        __syncthreads();
    }
    g_choff[t] = s[t] - orig;  // exclusive
}

// ---------------- scan phase 3: warp per chunk -> rowptr + work + dinv ----------------
__global__ void rowptr_dinv_kernel() {
    int warp = (blockIdx.x * blockDim.x + threadIdx.x) >> 5;
    int lane = threadIdx.x & 31;
    if (warp >= N_CHUNKS) return;
    int base = warp * 64;
    int c0 = g_count[base + lane];
    int c1 = g_count[base + 32 + lane];
    int i0 = c0, i1 = c1;
#pragma unroll
    for (int off = 1; off < 32; off <<= 1) {
        int v0 = __shfl_up_sync(0xffffffffu, i0, off);
        int v1 = __shfl_up_sync(0xffffffffu, i1, off);
        if (lane >= off) { i0 += v0; i1 += v1; }
    }
    int tot0 = __shfl_sync(0xffffffffu, i0, 31);
    int off = g_choff[warp];
    int r0 = off + i0 - c0;
    int r1 = off + tot0 + i1 - c1;
    g_rowptr[base + lane] = r0;
    g_rowptr[base + 32 + lane] = r1;
    g_work[base + lane] = r0;
    g_work[base + 32 + lane] = r1;
    if (warp == N_CHUNKS - 1 && lane == 31) g_rowptr[N_NODES] = N_EDGES;
    // dinv for the same 64 nodes (deg + 1.0 self loop)
    float d, r;
    d = 1.0f + g_deg[base + lane];
    r = rsqrtf(d);
    g_dinv[base + lane] = r * (1.5f - 0.5f * d * r * r);
    d = 1.0f + g_deg[base + 32 + lane];
    r = rsqrtf(d);
    g_dinv[base + 32 + lane] = r * (1.5f - 0.5f * d * r * r);
}

// ---------------- pass 3: fill CSR with normalized weights ----------------
__global__ void fill_kernel(const void* __restrict__ eidx,
                            const float* __restrict__ ew) {
    int e = blockIdx.x * blockDim.x + threadIdx.x;
    if (e >= N_EDGES) return;
    int src = load_idx(eidx, e);
    int dst = load_idx(eidx, N_EDGES + e);
    float w = ew[e] * g_dinv[src] * g_dinv[dst];
    int pos = atomicAdd(&g_work[dst], 1);
    g_csr[pos] = make_int2(src, __float_as_int(w));
}

// ---------------- GEMM: C[N,64] = A[N,K] @ W[K,64] ----------------
template <int K>
__global__ __launch_bounds__(256) void gemm_n64_kernel(
    const float* __restrict__ A, const float* __restrict__ W,
    float* __restrict__ C) {
    __shared__ float sw[K * 64];
    int tid = threadIdx.x, lane = tid & 31, warp = tid >> 5;
    for (int i = tid; i < K * 64; i += 256) sw[i] = W[i];
    __syncthreads();
    int row = blockIdx.x * 64 + warp * 8;
    for (int rr = 0; rr < 8; rr++, row++) {
        const float* a = A + (size_t)row * K;
        float ar[K / 32];
#pragma unroll
        for (int j = 0; j < K / 32; j++) ar[j] = a[lane + 32 * j];
        float acc0 = 0.f, acc1 = 0.f;
#pragma unroll
        for (int k = 0; k < K; k++) {
            float av = __shfl_sync(0xffffffffu, ar[k >> 5], k & 31);
            acc0 = fmaf(av, sw[k * 64 + lane], acc0);
            acc1 = fmaf(av, sw[k * 64 + lane + 32], acc1);
        }
        float* c = C + (size_t)row * 64;
        c[lane] = acc0;
        c[lane + 32] = acc1;
    }
}

// ---------------- aggregation + bias + ELU ----------------
// Warp per node. Each half-warp (16 lanes x float4) covers one full 64-float row,
// so the warp gathers 2 edges per iteration with one LDG.128 per lane.
__global__ __launch_bounds__(256) void agg_elu_kernel(
    const float* __restrict__ hw, const float* __restrict__ bias) {
    int node = (blockIdx.x * blockDim.x + threadIdx.x) >> 5;
    int lane = threadIdx.x & 31;
    if (node >= N_NODES) return;
    int half = lane >> 4;     // 0 or 1
    int l16 = lane & 15;
    const float4* hw4 = (const float4*)hw;  // row = 16 float4
    float4 acc = make_float4(0.f, 0.f, 0.f, 0.f);
    if (half == 0) {
        float di = g_dinv[node];
        float ws = di * di;
        float4 r = hw4[(size_t)node * 16 + l16];
        acc.x = ws * r.x; acc.y = ws * r.y; acc.z = ws * r.z; acc.w = ws * r.w;
    }
    int s0 = g_rowptr[node], s1 = g_rowptr[node + 1];
    for (int e = s0; e < s1; e += 2) {
        int ee = e + half;
        int2 m = (ee < s1) ? g_csr[ee] : make_int2(0, 0);  // w = 0.0f for pad
        float w = __int_as_float(m.y);
        float4 r = hw4[(size_t)m.x * 16 + l16];
        acc.x = fmaf(w, r.x, acc.x);
        acc.y = fmaf(w, r.y, acc.y);
        acc.z = fmaf(w, r.z, acc.z);
        acc.w = fmaf(w, r.w, acc.w);
    }
    // fold half 1 into half 0
    acc.x += __shfl_down_sync(0xffffffffu, acc.x, 16);
    acc.y += __shfl_down_sync(0xffffffffu, acc.y, 16);
    acc.z += __shfl_down_sync(0xffffffffu, acc.z, 16);
    acc.w += __shfl_down_sync(0xffffffffu, acc.w, 16);
    if (half == 0) {
        float4 bb = ((const float4*)bias)[l16];
        acc.x += bb.x; acc.y += bb.y; acc.z += bb.z; acc.w += bb.w;
        acc.x = acc.x > 0.f ? acc.x : expm1f(acc.x);
        acc.y = acc.y > 0.f ? acc.y : expm1f(acc.y);
        acc.z = acc.z > 0.f ? acc.z : expm1f(acc.z);
        acc.w = acc.w > 0.f ? acc.w : expm1f(acc.w);
        ((float4*)g_h)[(size_t)node * 16 + l16] = acc;
    }
}

// ---------------- final linear 64->32 + ReLU (warp per row) ----------------
__global__ __launch_bounds__(256) void final_lin_kernel(
    const float* __restrict__ W, const float* __restrict__ b,
    float* __restrict__ out) {
    __shared__ float sw[64 * 32];
    int tid = threadIdx.x, lane = tid & 31;
    for (int i = tid; i < 64 * 32; i += 256) sw[i] = W[i];
    __syncthreads();
    int row = (blockIdx.x * blockDim.x + tid) >> 5;
    if (row >= N_NODES) return;
    const float* h = g_h + (size_t)row * 64;
    float a0 = h[lane], a1 = h[lane + 32];
    float acc = b[lane];
#pragma unroll
    for (int k = 0; k < 64; k++) {
        float av = __shfl_sync(0xffffffffu, (k < 32) ? a0 : a1, k & 31);
        acc = fmaf(av, sw[k * 32 + lane], acc);
    }
    out[(size_t)row * 32 + lane] = acc > 0.f ? acc : 0.f;
}

// ---------------- launch ----------------
extern "C" void kernel_launch(void* const* d_in, const int* in_sizes, int n_in,
                              void* d_out, int out_size) {
    const float* x      = (const float*)d_in[0];
    const void*  eidx   = d_in[1];
    const float* ew     = (const float*)d_in[2];
    const float* W1     = (const float*)d_in[3];
    const float* b1     = (const float*)d_in[4];
    const float* W_hid  = (const float*)d_in[5];
    const float* b_hid  = (const float*)d_in[6];
    const float* W_lin  = (const float*)d_in[7];
    const float* b_lin  = (const float*)d_in[8];
    float* out = (float*)d_out;

    float *h_ptr, *hw_ptr;
    void *count_ptr, *deg_ptr;
    cudaGetSymbolAddress((void**)&h_ptr, g_h);
    cudaGetSymbolAddress((void**)&hw_ptr, g_hw);
    cudaGetSymbolAddress(&count_ptr, g_count);
    cudaGetSymbolAddress(&deg_ptr, g_deg);

    // ---- graph preprocessing ----
    detect_kernel<<<1, 128>>>((const unsigned int*)eidx);
    cudaMemsetAsync(count_ptr, 0, N_NODES * sizeof(int));
    cudaMemsetAsync(deg_ptr, 0, N_NODES * sizeof(float));
    count_deg_kernel<<<N_EDGES / 256, 256>>>(eidx, ew);
    chunk_reduce_kernel<<<N_CHUNKS / 8, 256>>>();
    scan_part_kernel<<<1, N_CHUNKS>>>();
    rowptr_dinv_kernel<<<N_CHUNKS / 8, 256>>>();
    fill_kernel<<<N_EDGES / 256, 256>>>(eidx, ew);

    // ---- layer 1: 128 -> 64 ----
    gemm_n64_kernel<IN_DIM><<<N_NODES / 64, 256>>>(x, W1, hw_ptr);
    agg_elu_kernel<<<N_NODES / 8, 256>>>(hw_ptr, b1);

    // ---- hidden layers: 64 -> 64 ----
    for (int l = 0; l < N_HIDDEN; l++) {
        gemm_n64_kernel<EMB><<<N_NODES / 64, 256>>>(
            h_ptr, W_hid + (size_t)l * EMB * EMB, hw_ptr);
        agg_elu_kernel<<<N_NODES / 8, 256>>>(hw_ptr, b_hid + (size_t)l * EMB);
    }

    // ---- final linear 64 -> 32 + ReLU ----
    final_lin_kernel<<<N_NODES / 8, 256>>>(W_lin, b_lin, out);
}